// round 7
// baseline (speedup 1.0000x reference)
#include <cuda_runtime.h>
#include <cuda_bf16.h>

#define B      512
#define DIM    128
#define MARGIN 0.2f
#define EPSF   1e-6f
#define BIGF   1e30f
#define SENTTH 1e29f
#define FULLM  0xffffffffu

#define LDJ 132   // Fj/u row stride in floats (16B-aligned, conflict-benign)
#define LDD 516   // D slab row stride in floats (16B-aligned)

// Accumulators (allocation-free rule). Statics init to zero; the last block
// resets them after use, so every graph replay starts from zero.
__device__ double g_num = 0.0;
__device__ unsigned long long g_den = 0ull;
__device__ unsigned int g_done = 0u;

// ---------------------------------------------------------------------------
// ONE fused kernel. Block b = anchor rows [4b, 4b+4). 128 threads = 4 warps.
// Phase A: compute the 4x512 distance slab into smem (norm expansion,
//          u_i = f_i + eps;  D^2 = |u|^2 + |f_j|^2 - 2 u.f_j).
// Phase B: warp w sorts row 4b+w (register-resident bitonic, R6-verified)
//          and accumulates the closed-form triplet sum.
// ---------------------------------------------------------------------------
__global__ __launch_bounds__(128) void fused_kernel(const float* __restrict__ F,
                                                    const int* __restrict__ mask,
                                                    float* __restrict__ out) {
    extern __shared__ float sm[];
    float* u_s  = sm;                       //   4 * 132
    float* Fj_s = u_s + 4 * LDJ;            // 128 * 132
    float* D_s  = Fj_s + 128 * LDJ;         //   4 * 516
    float* s_ni = D_s + 4 * LDD;            //   4
    float* s_bs = s_ni + 4;                 //   4
    unsigned long long* s_bd = (unsigned long long*)(s_bs + 4);  // 4 (8B-aligned)

    const int tid  = threadIdx.x;
    const int lane = tid & 31;
    const int warp = tid >> 5;
    const int i0   = blockIdx.x * 4;

    // ---- stage u = f(anchor rows) + eps ------------------------------------
    for (int idx = tid; idx < 4 * DIM; idx += 128) {
        const int r = idx >> 7, d = idx & 127;
        u_s[r * LDJ + d] = F[(i0 + r) * DIM + d] + EPSF;
    }
    __syncthreads();

    // ---- |u_i|^2 (warp w handles row w) ------------------------------------
    {
        float s = 0.f;
#pragma unroll
        for (int q = 0; q < 4; q++) {
            const float x = u_s[warp * LDJ + lane + 32 * q];
            s = fmaf(x, x, s);
        }
#pragma unroll
        for (int off = 16; off; off >>= 1) s += __shfl_down_sync(FULLM, s, off);
        if (lane == 0) s_ni[warp] = s;
    }

    // ---- Phase A: dot products over 4 j-tiles of 128 -----------------------
    float acc[4][4];   // [tile p][anchor i]
    float nf[4];       // |f_j|^2 for my j in each tile
#pragma unroll
    for (int p = 0; p < 4; p++) {
        nf[p] = 0.f;
#pragma unroll
        for (int i = 0; i < 4; i++) acc[p][i] = 0.f;
    }

    const float4* F4 = (const float4*)F;
    const float4* u0 = (const float4*)&u_s[0 * LDJ];
    const float4* u1 = (const float4*)&u_s[1 * LDJ];
    const float4* u2 = (const float4*)&u_s[2 * LDJ];
    const float4* u3 = (const float4*)&u_s[3 * LDJ];

#pragma unroll
    for (int p = 0; p < 4; p++) {
        __syncthreads();   // protect Fj_s reuse across tiles
        // stage tile rows [128p, 128p+128): coalesced LDG.128, floor-rate STS.128
#pragma unroll 4
        for (int k = 0; k < 32; k++) {
            const int idx = tid + (k << 7);
            const int r = idx >> 5, c = idx & 31;
            const float4 fv = F4[(128 * p + r) * 32 + c];
            *(float4*)&Fj_s[r * LDJ + 4 * c] = fv;
        }
        __syncthreads();

        const float4* fjrow = (const float4*)&Fj_s[tid * LDJ];  // my j = 128p + tid
#pragma unroll 8
        for (int dq = 0; dq < 32; dq++) {
            const float4 fv = fjrow[dq];
            nf[p] = fmaf(fv.x, fv.x, fmaf(fv.y, fv.y,
                    fmaf(fv.z, fv.z, fmaf(fv.w, fv.w, nf[p]))));
            const float4 a = u0[dq];
            acc[p][0] = fmaf(a.x, fv.x, fmaf(a.y, fv.y,
                        fmaf(a.z, fv.z, fmaf(a.w, fv.w, acc[p][0]))));
            const float4 b = u1[dq];
            acc[p][1] = fmaf(b.x, fv.x, fmaf(b.y, fv.y,
                        fmaf(b.z, fv.z, fmaf(b.w, fv.w, acc[p][1]))));
            const float4 c4 = u2[dq];
            acc[p][2] = fmaf(c4.x, fv.x, fmaf(c4.y, fv.y,
                        fmaf(c4.z, fv.z, fmaf(c4.w, fv.w, acc[p][2]))));
            const float4 e = u3[dq];
            acc[p][3] = fmaf(e.x, fv.x, fmaf(e.y, fv.y,
                        fmaf(e.z, fv.z, fmaf(e.w, fv.w, acc[p][3]))));
        }
    }

    // ---- epilogue: D slab into smem -----------------------------------------
#pragma unroll
    for (int i = 0; i < 4; i++) {
        const float ni = s_ni[i];
#pragma unroll
        for (int p = 0; p < 4; p++) {
            const float d2 = ni + nf[p] - 2.f * acc[p][i];
            D_s[i * LDD + p * 128 + tid] = sqrtf(fmaxf(d2, 0.f));
        }
    }
    __syncthreads();

    // =========================================================================
    // Phase B: warp w owns row i = i0 + warp. 512 keys register-resident,
    // element e = lane*16 + r. LSB tag: pos=(d+margin)|1, neg=d&~1,
    // diag-excluded = BIGF (value-guarded out of float sums — R5 lesson).
    // =========================================================================
    const int i = i0 + warp;
    float v[16];
    int npos = 0, nneg = 0;
    const int4* Mrow = (const int4*)(mask + i * B);

#pragma unroll
    for (int q = 0; q < 4; q++) {
        const float4 d4 = *(const float4*)&D_s[warp * LDD + lane * 16 + 4 * q];
        const int4   m4 = Mrow[lane * 4 + q];
        const float dv[4] = {d4.x, d4.y, d4.z, d4.w};
        const int   mv[4] = {m4.x, m4.y, m4.z, m4.w};
#pragma unroll
        for (int t = 0; t < 4; t++) {
            const int j = lane * 16 + q * 4 + t;
            unsigned kb;
            if (mv[t] != 0) {                 // positive
                kb = __float_as_uint(dv[t] + MARGIN) | 1u;
                npos++;
            } else if (j == i) {              // excluded diagonal -> sentinel
                kb = __float_as_uint(BIGF) & ~1u;
            } else {                          // negative
                kb = __float_as_uint(dv[t]) & ~1u;
                nneg++;
            }
            v[q * 4 + t] = __uint_as_float(kb);
        }
    }
    const int np = __reduce_add_sync(FULLM, npos);
    const int nn = __reduce_add_sync(FULLM, nneg);

    // ---- bitonic sort of 512 keys, ascending (register + shfl only) ---------
#pragma unroll
    for (int k = 2; k <= 512; k <<= 1) {
        const bool asc_lane_valid = (k >= 16);
        const bool asc_l = ((lane & (k >> 4)) == 0);
#pragma unroll
        for (int j = k >> 1; j >= 1; j >>= 1) {
            if (j >= 16) {
                const int jl = j >> 4;
                const bool keep_min = (((lane & jl) == 0) == asc_l);
#pragma unroll
                for (int r = 0; r < 16; r++) {
                    const float pv = __shfl_xor_sync(FULLM, v[r], jl);
                    v[r] = keep_min ? fminf(v[r], pv) : fmaxf(v[r], pv);
                }
            } else {
#pragma unroll
                for (int r = 0; r < 16; r++) {
                    if ((r & j) == 0) {
                        const int r2 = r | j;
                        const bool asc = asc_lane_valid ? asc_l : ((r & k) == 0);
                        const float a = v[r], bb = v[r2];
                        const float lo = fminf(a, bb), hi = fmaxf(a, bb);
                        v[r]  = asc ? lo : hi;
                        v[r2] = asc ? hi : lo;
                    }
                }
            }
        }
    }

    // ---- pass 1: per-lane totals of negatives (value-guarded) ---------------
    float runs = 0.f;
    int   runc = 0;
#pragma unroll
    for (int r = 0; r < 16; r++) {
        const bool isneg = ((__float_as_uint(v[r]) & 1u) == 0) && (v[r] < SENTTH);
        if (isneg) { runs += v[r]; runc++; }
    }
    float ls = runs;
    int   lc = runc;
#pragma unroll
    for (int off = 1; off < 32; off <<= 1) {
        const float y = __shfl_up_sync(FULLM, ls, off);
        const int   z = __shfl_up_sync(FULLM, lc, off);
        if (lane >= off) { ls += y; lc += z; }
    }
    float rs = ls - runs;
    int   rc = lc - runc;

    // ---- pass 2: positive contributions --------------------------------------
    float local = 0.f;
#pragma unroll
    for (int r = 0; r < 16; r++) {
        const bool ispos = (__float_as_uint(v[r]) & 1u) != 0;
        if (ispos) {
            local += (float)rc * v[r] - rs;
        } else if (v[r] < SENTTH) {
            rs += v[r];
            rc++;
        }
    }

    // ---- warp reduce + block combine + finalize ------------------------------
#pragma unroll
    for (int off = 16; off; off >>= 1)
        local += __shfl_down_sync(FULLM, local, off);

    if (lane == 0) {
        s_bs[warp] = local;
        s_bd[warp] = (unsigned long long)np * (unsigned long long)nn;
    }
    __syncthreads();

    if (tid == 0) {
        const float s = s_bs[0] + s_bs[1] + s_bs[2] + s_bs[3];
        const unsigned long long d = s_bd[0] + s_bd[1] + s_bd[2] + s_bd[3];
        atomicAdd(&g_num, (double)s);
        atomicAdd(&g_den, d);
        __threadfence();
        const unsigned int ticket = atomicAdd(&g_done, 1u);
        if (ticket == gridDim.x - 1) {
            const double num = atomicAdd(&g_num, 0.0);
            const unsigned long long den = atomicAdd(&g_den, 0ull);
            out[0] = (den > 0ull) ? (float)(num / (double)den) : 0.0f;
            g_num  = 0.0;
            g_den  = 0ull;
            __threadfence();
            g_done = 0u;
        }
    }
}

// ---------------------------------------------------------------------------
extern "C" void kernel_launch(void* const* d_in, const int* in_sizes, int n_in,
                              void* d_out, int out_size) {
    const float* features = (const float*)d_in[0];   // [512,128] f32
    const int*   mask     = (const int*)d_in[1];     // [512,512] i32
    float* out = (float*)d_out;

    const int smem_bytes =
        (4 * LDJ + 128 * LDJ + 4 * LDD + 4 + 4) * (int)sizeof(float)
        + 4 * (int)sizeof(unsigned long long);
    static bool attr_set = false;
    if (!attr_set) {
        cudaFuncSetAttribute(fused_kernel, cudaFuncAttributeMaxDynamicSharedMemorySize,
                             smem_bytes);
        attr_set = true;
    }

    fused_kernel<<<B / 4, 128, smem_bytes>>>(features, mask, out);
}

// round 8
// speedup vs baseline: 1.3378x; 1.3378x over previous
#include <cuda_runtime.h>
#include <cuda_bf16.h>

#define B      512
#define DIM    128
#define MARGIN 0.2f
#define EPSF   1e-6f
#define BIGF   1e30f
#define SENTTH 1e29f
#define FULLM  0xffffffffu

#define LDJ 132   // Fj/u row stride in floats (16B-aligned, conflict-free LDS.128)
#define LDD 516   // D slab row stride in floats
#define TJ  256   // j-tile size (2 tiles cover B=512)

// Accumulators (allocation-free rule). Statics init to zero; the last block
// resets them after use, so every graph replay starts from zero.
__device__ double g_num = 0.0;
__device__ unsigned long long g_den = 0ull;
__device__ unsigned int g_done = 0u;

// ---------------------------------------------------------------------------
// ONE fused kernel, 256 threads (8 warps). Block b = anchor rows [4b, 4b+4).
// Phase A (all 8 warps): 4x512 distance slab into smem via norm expansion,
//   u_i = f_i + eps;  D^2 = |u|^2 + |f_j|^2 - 2 u.f_j.  Thread t owns j-column
//   t within each of 2 tiles of 256.
// Phase B (warps 0-3): warp w sorts row 4b+w register-resident (R6-verified
//   bitonic + LSB tag + closed-form prefix), accumulates loss.
// ---------------------------------------------------------------------------
__global__ __launch_bounds__(256) void fused_kernel(const float* __restrict__ F,
                                                    const int* __restrict__ mask,
                                                    float* __restrict__ out) {
    extern __shared__ float sm[];
    float* u_s  = sm;                       //   4 * 132
    float* Fj_s = u_s + 4 * LDJ;            // 256 * 132
    float* D_s  = Fj_s + TJ * LDJ;          //   4 * 516
    float* s_ni = D_s + 4 * LDD;            //   4
    float* s_bs = s_ni + 4;                 //   4
    unsigned long long* s_bd = (unsigned long long*)(s_bs + 4);  // 4

    const int tid  = threadIdx.x;
    const int lane = tid & 31;
    const int warp = tid >> 5;
    const int i0   = blockIdx.x * 4;

    // ---- prefetch mask row for my sort row (hides cold-DRAM latency) -------
    int4 m4p[4];
    if (warp < 4) {
        const int4* Mrow = (const int4*)(mask + (i0 + warp) * B);
#pragma unroll
        for (int q = 0; q < 4; q++) m4p[q] = Mrow[lane * 4 + q];
    }

    // ---- stage u = f(anchor rows) + eps -------------------------------------
    for (int idx = tid; idx < 4 * DIM; idx += 256) {
        const int r = idx >> 7, d = idx & 127;
        u_s[r * LDJ + d] = F[(i0 + r) * DIM + d] + EPSF;
    }
    __syncthreads();

    // ---- |u_i|^2 (warps 0-3, warp w -> row w) -------------------------------
    if (warp < 4) {
        float s = 0.f;
#pragma unroll
        for (int q = 0; q < 4; q++) {
            const float x = u_s[warp * LDJ + lane + 32 * q];
            s = fmaf(x, x, s);
        }
#pragma unroll
        for (int off = 16; off; off >>= 1) s += __shfl_down_sync(FULLM, s, off);
        if (lane == 0) s_ni[warp] = s;
    }

    // ---- Phase A: 2 j-tiles of 256 ------------------------------------------
    float acc[2][4];
    float nf[2];
#pragma unroll
    for (int p = 0; p < 2; p++) {
        nf[p] = 0.f;
#pragma unroll
        for (int i = 0; i < 4; i++) acc[p][i] = 0.f;
    }

    const float4* F4 = (const float4*)F;
    const float4* u0 = (const float4*)&u_s[0 * LDJ];
    const float4* u1 = (const float4*)&u_s[1 * LDJ];
    const float4* u2 = (const float4*)&u_s[2 * LDJ];
    const float4* u3 = (const float4*)&u_s[3 * LDJ];

#pragma unroll
    for (int p = 0; p < 2; p++) {
        __syncthreads();   // protect Fj_s reuse across tiles
        // stage tile rows [256p, 256p+256): coalesced LDG.128 -> STS.128
#pragma unroll 4
        for (int k = 0; k < 32; k++) {
            const int idx = tid + (k << 8);
            const int r = idx >> 5, c = idx & 31;      // 8 rows per iteration
            const float4 fv = F4[(TJ * p + r) * 32 + c];
            *(float4*)&Fj_s[r * LDJ + 4 * c] = fv;
        }
        __syncthreads();

        const float4* fjrow = (const float4*)&Fj_s[tid * LDJ];  // my j = 256p + tid
#pragma unroll 8
        for (int dq = 0; dq < 32; dq++) {
            const float4 fv = fjrow[dq];
            nf[p] = fmaf(fv.x, fv.x, fmaf(fv.y, fv.y,
                    fmaf(fv.z, fv.z, fmaf(fv.w, fv.w, nf[p]))));
            const float4 a = u0[dq];
            acc[p][0] = fmaf(a.x, fv.x, fmaf(a.y, fv.y,
                        fmaf(a.z, fv.z, fmaf(a.w, fv.w, acc[p][0]))));
            const float4 b = u1[dq];
            acc[p][1] = fmaf(b.x, fv.x, fmaf(b.y, fv.y,
                        fmaf(b.z, fv.z, fmaf(b.w, fv.w, acc[p][1]))));
            const float4 c4 = u2[dq];
            acc[p][2] = fmaf(c4.x, fv.x, fmaf(c4.y, fv.y,
                        fmaf(c4.z, fv.z, fmaf(c4.w, fv.w, acc[p][2]))));
            const float4 e = u3[dq];
            acc[p][3] = fmaf(e.x, fv.x, fmaf(e.y, fv.y,
                        fmaf(e.z, fv.z, fmaf(e.w, fv.w, acc[p][3]))));
        }
    }

    // ---- epilogue: D slab ----------------------------------------------------
#pragma unroll
    for (int i = 0; i < 4; i++) {
        const float ni = s_ni[i];
#pragma unroll
        for (int p = 0; p < 2; p++) {
            const float d2 = ni + nf[p] - 2.f * acc[p][i];
            D_s[i * LDD + p * TJ + tid] = sqrtf(fmaxf(d2, 0.f));
        }
    }
    __syncthreads();

    // =========================================================================
    // Phase B (warps 0-3): register-resident sort of row i0+warp.
    // Element e = lane*16 + r. LSB tag: pos=(d+margin)|1, neg=d&~1,
    // excluded diagonal = BIGF (value-guarded out of float sums).
    // =========================================================================
    if (warp < 4) {
        const int i = i0 + warp;
        float v[16];
        int npos = 0, nneg = 0;

#pragma unroll
        for (int q = 0; q < 4; q++) {
            const float4 d4 = *(const float4*)&D_s[warp * LDD + lane * 16 + 4 * q];
            const float dv[4] = {d4.x, d4.y, d4.z, d4.w};
            const int   mv[4] = {m4p[q].x, m4p[q].y, m4p[q].z, m4p[q].w};
#pragma unroll
            for (int t = 0; t < 4; t++) {
                const int j = lane * 16 + q * 4 + t;
                unsigned kb;
                if (mv[t] != 0) {                 // positive
                    kb = __float_as_uint(dv[t] + MARGIN) | 1u;
                    npos++;
                } else if (j == i) {              // excluded diagonal
                    kb = __float_as_uint(BIGF) & ~1u;
                } else {                          // negative
                    kb = __float_as_uint(dv[t]) & ~1u;
                    nneg++;
                }
                v[q * 4 + t] = __uint_as_float(kb);
            }
        }
        const int np = __reduce_add_sync(FULLM, npos);
        const int nn = __reduce_add_sync(FULLM, nneg);

        // bitonic sort, ascending
#pragma unroll
        for (int k = 2; k <= 512; k <<= 1) {
            const bool asc_lane_valid = (k >= 16);
            const bool asc_l = ((lane & (k >> 4)) == 0);
#pragma unroll
            for (int j = k >> 1; j >= 1; j >>= 1) {
                if (j >= 16) {
                    const int jl = j >> 4;
                    const bool keep_min = (((lane & jl) == 0) == asc_l);
#pragma unroll
                    for (int r = 0; r < 16; r++) {
                        const float pv = __shfl_xor_sync(FULLM, v[r], jl);
                        v[r] = keep_min ? fminf(v[r], pv) : fmaxf(v[r], pv);
                    }
                } else {
#pragma unroll
                    for (int r = 0; r < 16; r++) {
                        if ((r & j) == 0) {
                            const int r2 = r | j;
                            const bool asc = asc_lane_valid ? asc_l : ((r & k) == 0);
                            const float a = v[r], bb = v[r2];
                            const float lo = fminf(a, bb), hi = fmaxf(a, bb);
                            v[r]  = asc ? lo : hi;
                            v[r2] = asc ? hi : lo;
                        }
                    }
                }
            }
        }

        // pass 1: per-lane negative (sum, count), sentinel value-guarded
        float runs = 0.f;
        int   runc = 0;
#pragma unroll
        for (int r = 0; r < 16; r++) {
            const bool isneg = ((__float_as_uint(v[r]) & 1u) == 0) && (v[r] < SENTTH);
            if (isneg) { runs += v[r]; runc++; }
        }
        float ls = runs;
        int   lc = runc;
#pragma unroll
        for (int off = 1; off < 32; off <<= 1) {
            const float y = __shfl_up_sync(FULLM, ls, off);
            const int   z = __shfl_up_sync(FULLM, lc, off);
            if (lane >= off) { ls += y; lc += z; }
        }
        float rs = ls - runs;
        int   rc = lc - runc;

        // pass 2: positive contributions
        float local = 0.f;
#pragma unroll
        for (int r = 0; r < 16; r++) {
            const bool ispos = (__float_as_uint(v[r]) & 1u) != 0;
            if (ispos) {
                local += (float)rc * v[r] - rs;
            } else if (v[r] < SENTTH) {
                rs += v[r];
                rc++;
            }
        }

#pragma unroll
        for (int off = 16; off; off >>= 1)
            local += __shfl_down_sync(FULLM, local, off);

        if (lane == 0) {
            s_bs[warp] = local;
            s_bd[warp] = (unsigned long long)np * (unsigned long long)nn;
        }
    }
    __syncthreads();

    if (tid == 0) {
        const float s = s_bs[0] + s_bs[1] + s_bs[2] + s_bs[3];
        const unsigned long long d = s_bd[0] + s_bd[1] + s_bd[2] + s_bd[3];
        atomicAdd(&g_num, (double)s);
        atomicAdd(&g_den, d);
        __threadfence();
        const unsigned int ticket = atomicAdd(&g_done, 1u);
        if (ticket == gridDim.x - 1) {
            const double num = atomicAdd(&g_num, 0.0);
            const unsigned long long den = atomicAdd(&g_den, 0ull);
            out[0] = (den > 0ull) ? (float)(num / (double)den) : 0.0f;
            g_num  = 0.0;
            g_den  = 0ull;
            __threadfence();
            g_done = 0u;
        }
    }
}

// ---------------------------------------------------------------------------
extern "C" void kernel_launch(void* const* d_in, const int* in_sizes, int n_in,
                              void* d_out, int out_size) {
    const float* features = (const float*)d_in[0];   // [512,128] f32
    const int*   mask     = (const int*)d_in[1];     // [512,512] i32
    float* out = (float*)d_out;

    const int smem_bytes =
        (4 * LDJ + TJ * LDJ + 4 * LDD + 4 + 4) * (int)sizeof(float)
        + 4 * (int)sizeof(unsigned long long);
    static bool attr_set = false;
    if (!attr_set) {
        cudaFuncSetAttribute(fused_kernel, cudaFuncAttributeMaxDynamicSharedMemorySize,
                             smem_bytes);
        attr_set = true;
    }

    fused_kernel<<<B / 4, 256, smem_bytes>>>(features, mask, out);
}

// round 9
// speedup vs baseline: 1.5000x; 1.1212x over previous
#include <cuda_runtime.h>
#include <cuda_bf16.h>

#define B      512
#define DIM    128
#define MARGIN 0.2f
#define EPSF   1e-6f
#define BIGF   1e30f
#define SENTTH 1e29f
#define FULLM  0xffffffffu

#define LDJ 132   // Fj/u row stride (floats): 16B-aligned, quarter-warp conflict-free
#define LDD 516   // D slab row stride (floats)
#define TJ  256   // j-tile size (2 tiles cover B=512)
#define NT  512   // threads per block

// Accumulators (allocation-free rule). Statics init to zero; the last block
// resets them after use, so every graph replay starts from zero.
__device__ double g_num = 0.0;
__device__ unsigned long long g_den = 0ull;
__device__ unsigned int g_done = 0u;

// ---------------------------------------------------------------------------
// ONE fused kernel, 512 threads (16 warps). Block b = anchor rows [4b, 4b+4).
// Phase A: 4x512 distance slab via norm expansion. Thread (h, jl) with
//   h = tid/256, jl = tid%256 computes the HALF-dot over d in [64h, 64h+64)
//   for j-column jl of each tile; halves combine via smem scratch.
// Phase B (warps 0-3): register-resident bitonic sort per row (R6-verified),
//   closed-form triplet sum, single atomic finalize.
// ---------------------------------------------------------------------------
__global__ __launch_bounds__(NT) void fused_kernel(const float* __restrict__ F,
                                                   const int* __restrict__ mask,
                                                   float* __restrict__ out) {
    extern __shared__ float sm[];
    float* u_s    = sm;                        //   4 * 132
    float* Fj_s   = u_s + 4 * LDJ;             // 256 * 132
    float* D_s    = Fj_s + TJ * LDJ;           //   4 * 516
    float* s_ni   = D_s + 4 * LDD;             //   4
    float* s_part = s_ni + 4;                  // 256 * 6 (h=1 partials)
    float* s_bs   = s_part + 256 * 6;          //   4
    unsigned long long* s_bd = (unsigned long long*)(s_bs + 4);   // 4

    const int tid  = threadIdx.x;
    const int lane = tid & 31;
    const int warp = tid >> 5;
    const int i0   = blockIdx.x * 4;
    const int h    = tid >> 8;        // d-half owner (uniform per warp)
    const int jl   = tid & 255;       // j column within tile

    // ---- prefetch mask row for my sort row (warps 0-3) ----------------------
    int4 m4p[4];
    if (warp < 4) {
        const int4* Mrow = (const int4*)(mask + (i0 + warp) * B);
#pragma unroll
        for (int q = 0; q < 4; q++) m4p[q] = Mrow[lane * 4 + q];
    }

    // ---- stage u = f(anchor rows) + eps --------------------------------------
    for (int idx = tid; idx < 4 * DIM; idx += NT) {
        const int r = idx >> 7, d = idx & 127;
        u_s[r * LDJ + d] = F[(i0 + r) * DIM + d] + EPSF;
    }
    __syncthreads();

    // ---- |u_i|^2 (warps 0-3; warp w -> row w) --------------------------------
    if (warp < 4) {
        float s = 0.f;
#pragma unroll
        for (int q = 0; q < 4; q++) {
            const float x = u_s[warp * LDJ + lane + 32 * q];
            s = fmaf(x, x, s);
        }
#pragma unroll
        for (int off = 16; off; off >>= 1) s += __shfl_down_sync(FULLM, s, off);
        if (lane == 0) s_ni[warp] = s;
    }

    const float4* F4 = (const float4*)F;
    // u half-rows for my h (broadcast LDS within warp)
    const float4* u0 = (const float4*)&u_s[0 * LDJ + 64 * h];
    const float4* u1 = (const float4*)&u_s[1 * LDJ + 64 * h];
    const float4* u2 = (const float4*)&u_s[2 * LDJ + 64 * h];
    const float4* u3 = (const float4*)&u_s[3 * LDJ + 64 * h];

    // ---- Phase A: 2 j-tiles of 256 -------------------------------------------
#pragma unroll
    for (int p = 0; p < 2; p++) {
        __syncthreads();   // protect Fj_s + s_part reuse across tiles
        // stage tile rows [256p, 256p+256): coalesced LDG.128 -> STS.128
#pragma unroll
        for (int k = 0; k < 16; k++) {
            const int idx = tid + (k << 9);
            const int r = idx >> 5, c = idx & 31;
            const float4 fv = F4[(TJ * p + r) * 32 + c];
            *(float4*)&Fj_s[r * LDJ + 4 * c] = fv;
        }
        __syncthreads();

        float acc0 = 0.f, acc1 = 0.f, acc2 = 0.f, acc3 = 0.f, nf = 0.f;
        const float4* fjrow = (const float4*)&Fj_s[jl * LDJ + 64 * h];
#pragma unroll
        for (int dq = 0; dq < 16; dq++) {
            const float4 fv = fjrow[dq];
            nf   = fmaf(fv.x, fv.x, fmaf(fv.y, fv.y,
                   fmaf(fv.z, fv.z, fmaf(fv.w, fv.w, nf))));
            const float4 a = u0[dq];
            acc0 = fmaf(a.x, fv.x, fmaf(a.y, fv.y,
                   fmaf(a.z, fv.z, fmaf(a.w, fv.w, acc0))));
            const float4 b = u1[dq];
            acc1 = fmaf(b.x, fv.x, fmaf(b.y, fv.y,
                   fmaf(b.z, fv.z, fmaf(b.w, fv.w, acc1))));
            const float4 c4 = u2[dq];
            acc2 = fmaf(c4.x, fv.x, fmaf(c4.y, fv.y,
                   fmaf(c4.z, fv.z, fmaf(c4.w, fv.w, acc2))));
            const float4 e = u3[dq];
            acc3 = fmaf(e.x, fv.x, fmaf(e.y, fv.y,
                   fmaf(e.z, fv.z, fmaf(e.w, fv.w, acc3))));
        }

        // combine halves: h=1 publishes partials; h=0 finishes + writes D
        if (h == 1) {
            float* dst = &s_part[jl * 6];
            dst[0] = acc0; dst[1] = acc1; dst[2] = acc2; dst[3] = acc3; dst[4] = nf;
        }
        __syncthreads();
        if (h == 0) {
            const float* src = &s_part[jl * 6];
            const float A0 = acc0 + src[0];
            const float A1 = acc1 + src[1];
            const float A2 = acc2 + src[2];
            const float A3 = acc3 + src[3];
            const float NF = nf   + src[4];
            const int jc = p * TJ + jl;
            float d2;
            d2 = s_ni[0] + NF - 2.f * A0; D_s[0 * LDD + jc] = sqrtf(fmaxf(d2, 0.f));
            d2 = s_ni[1] + NF - 2.f * A1; D_s[1 * LDD + jc] = sqrtf(fmaxf(d2, 0.f));
            d2 = s_ni[2] + NF - 2.f * A2; D_s[2 * LDD + jc] = sqrtf(fmaxf(d2, 0.f));
            d2 = s_ni[3] + NF - 2.f * A3; D_s[3 * LDD + jc] = sqrtf(fmaxf(d2, 0.f));
        }
    }
    __syncthreads();

    // =========================================================================
    // Phase B (warps 0-3): register-resident sort of row i0+warp.
    // Element e = lane*16 + r. LSB tag: pos=(d+margin)|1, neg=d&~1,
    // excluded diagonal = BIGF (value-guarded out of float sums).
    // =========================================================================
    if (warp < 4) {
        const int i = i0 + warp;
        float v[16];
        int npos = 0, nneg = 0;

#pragma unroll
        for (int q = 0; q < 4; q++) {
            const float4 d4 = *(const float4*)&D_s[warp * LDD + lane * 16 + 4 * q];
            const float dv[4] = {d4.x, d4.y, d4.z, d4.w};
            const int   mv[4] = {m4p[q].x, m4p[q].y, m4p[q].z, m4p[q].w};
#pragma unroll
            for (int t = 0; t < 4; t++) {
                const int j = lane * 16 + q * 4 + t;
                unsigned kb;
                if (mv[t] != 0) {
                    kb = __float_as_uint(dv[t] + MARGIN) | 1u;
                    npos++;
                } else if (j == i) {
                    kb = __float_as_uint(BIGF) & ~1u;
                } else {
                    kb = __float_as_uint(dv[t]) & ~1u;
                    nneg++;
                }
                v[q * 4 + t] = __uint_as_float(kb);
            }
        }
        const int np = __reduce_add_sync(FULLM, npos);
        const int nn = __reduce_add_sync(FULLM, nneg);

        // bitonic sort of 512 keys, ascending (register + shfl only)
#pragma unroll
        for (int k = 2; k <= 512; k <<= 1) {
            const bool asc_lane_valid = (k >= 16);
            const bool asc_l = ((lane & (k >> 4)) == 0);
#pragma unroll
            for (int j = k >> 1; j >= 1; j >>= 1) {
                if (j >= 16) {
                    const int jl2 = j >> 4;
                    const bool keep_min = (((lane & jl2) == 0) == asc_l);
#pragma unroll
                    for (int r = 0; r < 16; r++) {
                        const float pv = __shfl_xor_sync(FULLM, v[r], jl2);
                        v[r] = keep_min ? fminf(v[r], pv) : fmaxf(v[r], pv);
                    }
                } else {
#pragma unroll
                    for (int r = 0; r < 16; r++) {
                        if ((r & j) == 0) {
                            const int r2 = r | j;
                            const bool asc = asc_lane_valid ? asc_l : ((r & k) == 0);
                            const float a = v[r], bb = v[r2];
                            const float lo = fminf(a, bb), hi = fmaxf(a, bb);
                            v[r]  = asc ? lo : hi;
                            v[r2] = asc ? hi : lo;
                        }
                    }
                }
            }
        }

        // pass 1: per-lane negative (sum, count), sentinel value-guarded
        float runs = 0.f;
        int   runc = 0;
#pragma unroll
        for (int r = 0; r < 16; r++) {
            const bool isneg = ((__float_as_uint(v[r]) & 1u) == 0) && (v[r] < SENTTH);
            if (isneg) { runs += v[r]; runc++; }
        }
        float ls = runs;
        int   lc = runc;
#pragma unroll
        for (int off = 1; off < 32; off <<= 1) {
            const float y = __shfl_up_sync(FULLM, ls, off);
            const int   z = __shfl_up_sync(FULLM, lc, off);
            if (lane >= off) { ls += y; lc += z; }
        }
        float rs = ls - runs;
        int   rc = lc - runc;

        // pass 2: positive contributions
        float local = 0.f;
#pragma unroll
        for (int r = 0; r < 16; r++) {
            const bool ispos = (__float_as_uint(v[r]) & 1u) != 0;
            if (ispos) {
                local += (float)rc * v[r] - rs;
            } else if (v[r] < SENTTH) {
                rs += v[r];
                rc++;
            }
        }

#pragma unroll
        for (int off = 16; off; off >>= 1)
            local += __shfl_down_sync(FULLM, local, off);

        if (lane == 0) {
            s_bs[warp] = local;
            s_bd[warp] = (unsigned long long)np * (unsigned long long)nn;
        }
    }
    __syncthreads();

    if (tid == 0) {
        const float s = s_bs[0] + s_bs[1] + s_bs[2] + s_bs[3];
        const unsigned long long d = s_bd[0] + s_bd[1] + s_bd[2] + s_bd[3];
        atomicAdd(&g_num, (double)s);
        atomicAdd(&g_den, d);
        __threadfence();
        const unsigned int ticket = atomicAdd(&g_done, 1u);
        if (ticket == gridDim.x - 1) {
            const double num = atomicAdd(&g_num, 0.0);
            const unsigned long long den = atomicAdd(&g_den, 0ull);
            out[0] = (den > 0ull) ? (float)(num / (double)den) : 0.0f;
            g_num  = 0.0;
            g_den  = 0ull;
            __threadfence();
            g_done = 0u;
        }
    }
}

// ---------------------------------------------------------------------------
extern "C" void kernel_launch(void* const* d_in, const int* in_sizes, int n_in,
                              void* d_out, int out_size) {
    const float* features = (const float*)d_in[0];   // [512,128] f32
    const int*   mask     = (const int*)d_in[1];     // [512,512] i32
    float* out = (float*)d_out;

    const int smem_bytes =
        (4 * LDJ + TJ * LDJ + 4 * LDD + 4 + 256 * 6 + 4) * (int)sizeof(float)
        + 4 * (int)sizeof(unsigned long long);
    static bool attr_set = false;
    if (!attr_set) {
        cudaFuncSetAttribute(fused_kernel, cudaFuncAttributeMaxDynamicSharedMemorySize,
                             smem_bytes);
        attr_set = true;
    }

    fused_kernel<<<B / 4, NT, smem_bytes>>>(features, mask, out);
}